// round 2
// baseline (speedup 1.0000x reference)
#include <cuda_runtime.h>
#include <math.h>

#define BB 4
#define C 64
#define CQn 8
#define H 256
#define W 256
#define HW 65536
#define CHW (C*HW)          // 4194304
#define TOT (BB*CHW)        // 16777216

// ---------------- scratch (static device globals; no allocation) ----------------
__device__ float g_y0[TOT];            // pre-norm pointwise output
__device__ float g_val[TOT];           // v projection
__device__ float g_att[TOT];           // h_out (+ v_out) accumulator
__device__ float g_q[BB*CQn*HW];
__device__ float g_k[BB*CQn*HW];
__device__ float g_isum[BB*C], g_isq[BB*C];
__device__ float g_alpha[BB*C], g_beta[BB*C];

// ---------------- 1) axial depthwise conv + relu + 64x64 pointwise -> g_y0 ------
__global__ __launch_bounds__(256, 2)
void k_conv_pw(const float* __restrict__ x,
               const float* __restrict__ hw_, const float* __restrict__ hb,
               const float* __restrict__ vw_, const float* __restrict__ vb,
               const float* __restrict__ pww, const float* __restrict__ pwb) {
    __shared__ float s_hw[C*5], s_vw[C*5], s_hb[C], s_vb[C], s_pw[C*C], s_pwb[C];
    int tid = threadIdx.x;
    for (int i = tid; i < C*5; i += 256) { s_hw[i] = hw_[i]; s_vw[i] = vw_[i]; }
    for (int i = tid; i < C;   i += 256) { s_hb[i] = hb[i]; s_vb[i] = vb[i]; s_pwb[i] = pwb[i]; }
    for (int i = tid; i < C*C; i += 256) s_pw[i] = pww[i];
    __syncthreads();

    int row = blockIdx.x;          // b*H + h
    int b = row >> 8, h = row & 255;
    int w = tid;
    const float* xb = x + (size_t)b * CHW;

    float acc[C];
    #pragma unroll
    for (int o = 0; o < C; o++) acc[o] = s_pwb[o];

    for (int c = 0; c < C; c++) {
        const float* xc = xb + c * HW + h * W;
        float center = xc[w];
        float hs = s_hb[c], vs = s_vb[c];
        #pragma unroll
        for (int t = 0; t < 5; t++) {
            int ww = w + t - 2;
            float xv = (ww >= 0 && ww < W) ? xc[ww] : 0.f;
            hs = fmaf(s_hw[c*5 + t], xv, hs);
            int hh = h + t - 2;
            float xv2 = (hh >= 0 && hh < H) ? xb[c*HW + hh*W + w] : 0.f;
            vs = fmaf(s_vw[c*5 + t], xv2, vs);
        }
        float a = hs + vs + center;
        a = a > 0.f ? a : 0.f;
        #pragma unroll
        for (int o = 0; o < C; o++) acc[o] = fmaf(s_pw[o*C + c], a, acc[o]);
    }
    size_t base = (size_t)b * CHW + h * W + w;
    #pragma unroll
    for (int o = 0; o < C; o++) g_y0[base + (size_t)o * HW] = acc[o];
}

// ---------------- 2) per-(b,c) sum / sumsq ----------------
__global__ __launch_bounds__(256)
void k_istats() {
    int bc = blockIdx.x;
    int tid = threadIdx.x;
    const float4* p = (const float4*)(g_y0 + (size_t)bc * HW);
    float s = 0.f, q = 0.f;
    for (int i = tid; i < HW/4; i += 256) {
        float4 v = p[i];
        s += v.x + v.y + v.z + v.w;
        q += v.x*v.x + v.y*v.y + v.z*v.z + v.w*v.w;
    }
    __shared__ float ss[256], sq[256];
    ss[tid] = s; sq[tid] = q; __syncthreads();
    for (int o = 128; o > 0; o >>= 1) {
        if (tid < o) { ss[tid] += ss[tid+o]; sq[tid] += sq[tid+o]; }
        __syncthreads();
    }
    if (tid == 0) { g_isum[bc] = ss[0]; g_isq[bc] = sq[0]; }
}

// ---------------- 3) hybrid-norm -> per-(b,c) affine alpha,beta ----------------
__global__ void k_alphabeta(const float* __restrict__ bn_w, const float* __restrict__ bn_b) {
    int c = threadIdx.x;
    if (c >= C) return;
    const float EPS = 1e-5f, R = 0.7f, R1 = 0.3f;
    float im[BB], iv[BB];
    float bm = 0.f, ey2 = 0.f;
    for (int b = 0; b < BB; b++) {
        float s  = g_isum[b*C + c] * (1.0f/HW);
        float sq = g_isq [b*C + c] * (1.0f/HW);
        im[b] = s; iv[b] = sq - s*s;
        bm += s; ey2 += sq;
    }
    bm *= 0.25f; ey2 *= 0.25f;
    float bv = ey2 - bm*bm;
    float rB = rsqrtf(bv + EPS);
    float w = bn_w[c], bb = bn_b[c];
    for (int b = 0; b < BB; b++) {
        float rI = rsqrtf(iv[b] + EPS);
        g_alpha[b*C + c] = R*rI + R1*rB*w;
        g_beta [b*C + c] = -R*im[b]*rI + R1*(bb - bm*rB*w);
    }
}

// ---------------- 4) q/k/v projections from normalized y ----------------
__global__ __launch_bounds__(256, 2)
void k_qkv(const float* __restrict__ qw, const float* __restrict__ qb,
           const float* __restrict__ kw, const float* __restrict__ kb,
           const float* __restrict__ vw, const float* __restrict__ vb) {
    __shared__ float s_q[CQn*C], s_k[CQn*C], s_v[C*C];
    __shared__ float s_qb[CQn], s_kb[CQn], s_vb[C], s_al[C], s_be[C];
    int tid = threadIdx.x;
    int row = blockIdx.x;
    int b = row >> 8, h = row & 255;
    for (int i = tid; i < CQn*C; i += 256) { s_q[i] = qw[i]; s_k[i] = kw[i]; }
    for (int i = tid; i < C*C;   i += 256) s_v[i] = vw[i];
    if (tid < CQn) { s_qb[tid] = qb[tid]; s_kb[tid] = kb[tid]; }
    if (tid < C)   { s_vb[tid] = vb[tid]; s_al[tid] = g_alpha[b*C + tid]; s_be[tid] = g_beta[b*C + tid]; }
    __syncthreads();

    int pix = h * W + tid;
    size_t ybase = (size_t)b * CHW + pix;
    float y[C];
    #pragma unroll
    for (int c = 0; c < C; c++) y[c] = fmaf(s_al[c], g_y0[ybase + (size_t)c*HW], s_be[c]);

    size_t qbase = (size_t)b * CQn * HW + pix;
    #pragma unroll
    for (int o = 0; o < CQn; o++) {
        float aq = s_qb[o], ak = s_kb[o];
        #pragma unroll
        for (int c = 0; c < C; c++) {
            aq = fmaf(s_q[o*C + c], y[c], aq);
            ak = fmaf(s_k[o*C + c], y[c], ak);
        }
        g_q[qbase + (size_t)o*HW] = aq;
        g_k[qbase + (size_t)o*HW] = ak;
    }
    size_t vbase = (size_t)b * CHW + pix;
    for (int o0 = 0; o0 < C; o0 += 8) {
        float a8[8];
        #pragma unroll
        for (int u = 0; u < 8; u++) a8[u] = s_vb[o0 + u];
        #pragma unroll
        for (int c = 0; c < C; c++) {
            float yv = y[c];
            #pragma unroll
            for (int u = 0; u < 8; u++) a8[u] = fmaf(s_v[(o0+u)*C + c], yv, a8[u]);
        }
        #pragma unroll
        for (int u = 0; u < 8; u++) g_val[vbase + (size_t)(o0+u)*HW] = a8[u];
    }
}

// ---------------- 5) criss-cross attention, one (b, line) per CTA ----------------
// height pass: st = W, off0 = f  (lines are columns);   writes g_att
// width  pass: st = 1, off0 = f*W (lines are rows);     adds to g_att
__global__ __launch_bounds__(256, 2)
void k_attn(int st, int height, int add) {
    extern __shared__ float sm[];
    float* q_s = sm;            // 8 x 256
    float* k_s = sm + 2048;     // 8 x 256
    float* m_s = sm + 4096;     // 256
    float* v_s = sm + 4352;     // 256 x 68 (padded)
    int tid = threadIdx.x;
    int b = blockIdx.x >> 8;
    int f = blockIdx.x & 255;
    int off0 = height ? f : f * W;

    const float* qp = g_q   + (size_t)b * CQn * HW + off0;
    const float* kp = g_k   + (size_t)b * CQn * HW + off0;
    const float* vp = g_val + (size_t)b * CHW      + off0;
    float*       ap = g_att + (size_t)b * CHW      + off0;

    float qr[CQn], kr[CQn];
    #pragma unroll
    for (int c = 0; c < CQn; c++) {
        float qv = qp[(size_t)c*HW + tid*st];
        float kv = kp[(size_t)c*HW + tid*st];
        qr[c] = qv; kr[c] = kv;
        q_s[c*256 + tid] = qv; k_s[c*256 + tid] = kv;
    }
    __syncthreads();

    // ---- pass 1: per-source-row j=tid: m_j, Z_j ----
    float m = -1e30f;
    for (int i = 0; i < 256; i++) {
        float s = 0.f;
        #pragma unroll
        for (int c = 0; c < CQn; c++) s = fmaf(qr[c], k_s[c*256 + i], s);
        m = fmaxf(m, s);
    }
    float z = 0.f;
    for (int i = 0; i < 256; i++) {
        float s = 0.f;
        #pragma unroll
        for (int c = 0; c < CQn; c++) s = fmaf(qr[c], k_s[c*256 + i], s);
        z += __expf(s - m);
    }
    float invz = 1.0f / z;
    m_s[tid] = m;
    // load value row j (all 64 channels), pre-scaled by 1/Z_j
    #pragma unroll 8
    for (int c = 0; c < C; c++)
        v_s[tid*68 + c] = vp[(size_t)c*HW + tid*st] * invz;
    __syncthreads();

    // ---- pass 2: output column i=tid: out[c,i] = sum_j valg[c,j] * exp(s_ji - m_j) ----
    float acc[C];
    #pragma unroll
    for (int c = 0; c < C; c++) acc[c] = 0.f;
    for (int j = 0; j < 256; j++) {
        float s = 0.f;
        #pragma unroll
        for (int c = 0; c < CQn; c++) s = fmaf(q_s[c*256 + j], kr[c], s);
        float e = __expf(s - m_s[j]);
        const float4* vrow = (const float4*)(v_s + j*68);
        #pragma unroll
        for (int c4 = 0; c4 < 16; c4++) {
            float4 v = vrow[c4];
            acc[c4*4+0] = fmaf(e, v.x, acc[c4*4+0]);
            acc[c4*4+1] = fmaf(e, v.y, acc[c4*4+1]);
            acc[c4*4+2] = fmaf(e, v.z, acc[c4*4+2]);
            acc[c4*4+3] = fmaf(e, v.w, acc[c4*4+3]);
        }
    }
    if (add) {
        #pragma unroll 8
        for (int c = 0; c < C; c++) ap[(size_t)c*HW + tid*st] += acc[c];
    } else {
        #pragma unroll 8
        for (int c = 0; c < C; c++) ap[(size_t)c*HW + tid*st] = acc[c];
    }
}

// ---------------- 6) residual + gamma, write out, 2x2 maxpool -> down ----------------
__global__ __launch_bounds__(128)
void k_final(const float* __restrict__ gamma, float* __restrict__ out) {
    int tid = threadIdx.x;                 // w2 in [0,128)
    int b = blockIdx.x >> 7;
    int h2 = blockIdx.x & 127;
    float gm = gamma[0];
    float* down = out + TOT;
    for (int c = 0; c < C; c++) {
        float al = g_alpha[b*C + c], be = g_beta[b*C + c];
        size_t p = (size_t)b*CHW + (size_t)c*HW + (size_t)(2*h2)*W + 2*tid;
        float o00 = fmaf(gm, g_att[p],       fmaf(al, g_y0[p],       be));
        float o01 = fmaf(gm, g_att[p+1],     fmaf(al, g_y0[p+1],     be));
        float o10 = fmaf(gm, g_att[p+W],     fmaf(al, g_y0[p+W],     be));
        float o11 = fmaf(gm, g_att[p+W+1],   fmaf(al, g_y0[p+W+1],   be));
        out[p] = o00; out[p+1] = o01; out[p+W] = o10; out[p+W+1] = o11;
        float mx = fmaxf(fmaxf(o00, o01), fmaxf(o10, o11));
        down[(size_t)b*(CHW/4) + (size_t)c*(HW/4) + h2*(W/2) + tid] = mx;
    }
}

// ---------------- launch ----------------
extern "C" void kernel_launch(void* const* d_in, const int* in_sizes, int n_in,
                              void* d_out, int out_size) {
    const float* x       = (const float*)d_in[0];
    const float* hconv_w = (const float*)d_in[1];
    const float* hconv_b = (const float*)d_in[2];
    const float* vconv_w = (const float*)d_in[3];
    const float* vconv_b = (const float*)d_in[4];
    const float* pw_w    = (const float*)d_in[5];
    const float* pw_b    = (const float*)d_in[6];
    const float* bn_w    = (const float*)d_in[7];
    const float* bn_b    = (const float*)d_in[8];
    const float* q_w     = (const float*)d_in[9];
    const float* q_b     = (const float*)d_in[10];
    const float* k_w     = (const float*)d_in[11];
    const float* k_b     = (const float*)d_in[12];
    const float* v_w     = (const float*)d_in[13];
    const float* v_b     = (const float*)d_in[14];
    const float* gamma   = (const float*)d_in[15];
    float* out = (float*)d_out;

    const int ATTN_SMEM = (2048 + 2048 + 256 + 256*68) * 4;   // 87040 B
    static bool attr_done = false;
    if (!attr_done) {
        cudaFuncSetAttribute(k_attn, cudaFuncAttributeMaxDynamicSharedMemorySize, ATTN_SMEM);
        attr_done = true;
    }

    k_conv_pw<<<BB*H, 256>>>(x, hconv_w, hconv_b, vconv_w, vconv_b, pw_w, pw_b);
    k_istats<<<BB*C, 256>>>();
    k_alphabeta<<<1, 64>>>(bn_w, bn_b);
    k_qkv<<<BB*H, 256>>>(q_w, q_b, k_w, k_b, v_w, v_b);
    k_attn<<<BB*256, 256, ATTN_SMEM>>>(W, 1, 0);   // height pass (columns), write
    k_attn<<<BB*256, 256, ATTN_SMEM>>>(1, 0, 1);   // width pass (rows), accumulate
    k_final<<<BB*(H/2), 128>>>(gamma, out);
}

// round 7
// speedup vs baseline: 1.9774x; 1.9774x over previous
#include <cuda_runtime.h>
#include <math.h>

#define BB 4
#define C 64
#define CQn 8
#define H 256
#define W 256
#define HW 65536
#define CHW (C*HW)          // 4194304
#define TOT (BB*CHW)        // 16777216

typedef unsigned long long u64;

// ---- packed f32x2 helpers ----
__device__ __forceinline__ u64 pk2(float a, float b) {
    u64 r;
    asm("mov.b64 %0, {%1, %2};" : "=l"(r) : "r"(__float_as_uint(a)), "r"(__float_as_uint(b)));
    return r;
}
__device__ __forceinline__ void upk2(u64 v, float& a, float& b) {
    unsigned lo, hi;
    asm("mov.b64 {%0, %1}, %2;" : "=r"(lo), "=r"(hi) : "l"(v));
    a = __uint_as_float(lo); b = __uint_as_float(hi);
}
__device__ __forceinline__ u64 fma2(u64 a, u64 b, u64 c) {
    u64 d;
    asm("fma.rn.f32x2 %0, %1, %2, %3;" : "=l"(d) : "l"(a), "l"(b), "l"(c));
    return d;
}
__device__ __forceinline__ u64 add2(u64 a, u64 b) {
    u64 d;
    asm("add.rn.f32x2 %0, %1, %2;" : "=l"(d) : "l"(a), "l"(b));
    return d;
}

// ---------------- scratch ----------------
__device__ float g_y0[TOT];                 // pre-norm pointwise output (NCHW)
__device__ float g_val[TOT];                // v projection (channels-last [b][h][w][c])
__device__ float g_att[TOT];                // h_out (channels-last [b][i][w][c])
__device__ float g_q[BB*HW*CQn];            // channels-last [b][h][w][8]
__device__ float g_k[BB*HW*CQn];
__device__ float g_isum[BB*C], g_isq[BB*C];
__device__ float g_alpha[BB*C], g_beta[BB*C];

// ---------------- 1) axial depthwise conv + relu + pointwise (f32x2) ----------------
__global__ __launch_bounds__(256, 2)
void k_conv_pw(const float* __restrict__ x,
               const float* __restrict__ hw_, const float* __restrict__ hb,
               const float* __restrict__ vw_, const float* __restrict__ vb,
               const float* __restrict__ pww, const float* __restrict__ pwb) {
    __shared__ float s_hw[C*5], s_vw[C*5], s_hb[C], s_vb[C];
    __shared__ float s_pwT[C*C];            // [c][o] transposed
    __shared__ u64   s_pwb2[C/2];
    int tid = threadIdx.x;
    for (int i = tid; i < C*5; i += 256) { s_hw[i] = hw_[i]; s_vw[i] = vw_[i]; }
    for (int i = tid; i < C;   i += 256) { s_hb[i] = hb[i]; s_vb[i] = vb[i]; }
    for (int i = tid; i < C*C; i += 256) { int o = i >> 6, c = i & 63; s_pwT[c*C + o] = pww[i]; }
    if (tid < C/2) s_pwb2[tid] = pk2(pwb[2*tid], pwb[2*tid+1]);
    __syncthreads();

    int row = blockIdx.x;
    int b = row >> 8, h = row & 255;
    int w = tid;
    const float* xb = x + (size_t)b * CHW;

    u64 acc[C/2];
    #pragma unroll
    for (int o = 0; o < C/2; o++) acc[o] = s_pwb2[o];

    for (int c = 0; c < C; c++) {
        const float* xc = xb + c * HW + h * W;
        float center = xc[w];
        float hs = s_hb[c], vs = s_vb[c];
        #pragma unroll
        for (int t = 0; t < 5; t++) {
            int ww = w + t - 2;
            float xv = (ww >= 0 && ww < W) ? xc[ww] : 0.f;
            hs = fmaf(s_hw[c*5 + t], xv, hs);
            int hh = h + t - 2;
            float xv2 = (hh >= 0 && hh < H) ? xb[c*HW + hh*W + w] : 0.f;
            vs = fmaf(s_vw[c*5 + t], xv2, vs);
        }
        float a = hs + vs + center;
        a = a > 0.f ? a : 0.f;
        u64 a2 = pk2(a, a);
        const u64* wr = (const u64*)(s_pwT + c*C);
        #pragma unroll
        for (int o = 0; o < C/2; o++) acc[o] = fma2(a2, wr[o], acc[o]);
    }
    size_t base = (size_t)b * CHW + h * W + w;
    #pragma unroll
    for (int o = 0; o < C/2; o++) {
        float a, bb; upk2(acc[o], a, bb);
        g_y0[base + (size_t)(2*o)   * HW] = a;
        g_y0[base + (size_t)(2*o+1) * HW] = bb;
    }
}

// ---------------- 2) per-(b,c) sum / sumsq ----------------
__global__ __launch_bounds__(256)
void k_istats() {
    int bc = blockIdx.x;
    int tid = threadIdx.x;
    const float4* p = (const float4*)(g_y0 + (size_t)bc * HW);
    float s = 0.f, q = 0.f;
    for (int i = tid; i < HW/4; i += 256) {
        float4 v = p[i];
        s += v.x + v.y + v.z + v.w;
        q += v.x*v.x + v.y*v.y + v.z*v.z + v.w*v.w;
    }
    __shared__ float ss[256], sq[256];
    ss[tid] = s; sq[tid] = q; __syncthreads();
    for (int o = 128; o > 0; o >>= 1) {
        if (tid < o) { ss[tid] += ss[tid+o]; sq[tid] += sq[tid+o]; }
        __syncthreads();
    }
    if (tid == 0) { g_isum[bc] = ss[0]; g_isq[bc] = sq[0]; }
}

// ---------------- 3) hybrid-norm -> per-(b,c) affine alpha,beta ----------------
__global__ void k_alphabeta(const float* __restrict__ bn_w, const float* __restrict__ bn_b) {
    int c = threadIdx.x;
    if (c >= C) return;
    const float EPS = 1e-5f, R = 0.7f, R1 = 0.3f;
    float im[BB], iv[BB];
    float bm = 0.f, ey2 = 0.f;
    for (int b = 0; b < BB; b++) {
        float s  = g_isum[b*C + c] * (1.0f/HW);
        float sq = g_isq [b*C + c] * (1.0f/HW);
        im[b] = s; iv[b] = sq - s*s;
        bm += s; ey2 += sq;
    }
    bm *= 0.25f; ey2 *= 0.25f;
    float bv = ey2 - bm*bm;
    float rB = rsqrtf(bv + EPS);
    float w = bn_w[c], bb = bn_b[c];
    for (int b = 0; b < BB; b++) {
        float rI = rsqrtf(iv[b] + EPS);
        g_alpha[b*C + c] = R*rI + R1*rB*w;
        g_beta [b*C + c] = -R*im[b]*rI + R1*(bb - bm*rB*w);
    }
}

// ---------------- 4) q/k/v projections (f32x2, channels-last out) ----------------
__global__ __launch_bounds__(256, 2)
void k_qkv(const float* __restrict__ qw, const float* __restrict__ qb,
           const float* __restrict__ kw, const float* __restrict__ kb,
           const float* __restrict__ vw, const float* __restrict__ vb) {
    extern __shared__ float sm[];
    float* s_wT    = sm;                    // 64 x 80 : [c][o]  o: 0-7 q, 8-15 k, 16-79 v
    float* s_stage = sm + C*80;             // 256 x 68 (padded)
    __shared__ float s_al[C], s_be[C];
    __shared__ u64   s_b2[40];
    int tid = threadIdx.x;
    int b = blockIdx.x >> 8, h = blockIdx.x & 255;

    for (int i = tid; i < CQn*C; i += 256) {
        int o = i >> 6, c = i & 63;
        s_wT[c*80 + o]     = qw[i];
        s_wT[c*80 + 8 + o] = kw[i];
    }
    for (int i = tid; i < C*C; i += 256) {
        int o = i >> 6, c = i & 63;
        s_wT[c*80 + 16 + o] = vw[i];
    }
    if (tid < 4)                 s_b2[tid] = pk2(qb[2*tid],        qb[2*tid+1]);
    else if (tid < 8)            s_b2[tid] = pk2(kb[2*(tid-4)],    kb[2*(tid-4)+1]);
    else if (tid < 40)           s_b2[tid] = pk2(vb[2*(tid-8)],    vb[2*(tid-8)+1]);
    if (tid < C) { s_al[tid] = g_alpha[b*C + tid]; s_be[tid] = g_beta[b*C + tid]; }
    __syncthreads();

    u64 acc[40];
    #pragma unroll
    for (int o = 0; o < 40; o++) acc[o] = s_b2[o];

    size_t ybase = (size_t)b * CHW + h * W + tid;
    for (int c = 0; c < C; c++) {
        float y = fmaf(s_al[c], g_y0[ybase + (size_t)c*HW], s_be[c]);
        u64 y2 = pk2(y, y);
        const u64* wr = (const u64*)(s_wT + c*80);
        #pragma unroll
        for (int o = 0; o < 40; o++) acc[o] = fma2(y2, wr[o], acc[o]);
    }

    // q, k: per-thread float4 writes (channels-last)
    size_t pq = ((size_t)b*HW + h*W + tid) * 8;
    {
        float a0,a1,a2,a3;
        upk2(acc[0], a0, a1); upk2(acc[1], a2, a3);
        *(float4*)(g_q + pq) = make_float4(a0,a1,a2,a3);
        upk2(acc[2], a0, a1); upk2(acc[3], a2, a3);
        *(float4*)(g_q + pq + 4) = make_float4(a0,a1,a2,a3);
        upk2(acc[4], a0, a1); upk2(acc[5], a2, a3);
        *(float4*)(g_k + pq) = make_float4(a0,a1,a2,a3);
        upk2(acc[6], a0, a1); upk2(acc[7], a2, a3);
        *(float4*)(g_k + pq + 4) = make_float4(a0,a1,a2,a3);
    }
    // v: stage to smem (padded), then cooperative coalesced store
    #pragma unroll
    for (int u = 0; u < 32; u++) {
        float a, bb; upk2(acc[8 + u], a, bb);
        s_stage[tid*68 + 2*u]     = a;
        s_stage[tid*68 + 2*u + 1] = bb;
    }
    __syncthreads();
    float4* gv = (float4*)(g_val + ((size_t)b*HW + h*W) * 64);
    for (int e = tid; e < 4096; e += 256) {
        int p = e >> 4, c4 = e & 15;
        gv[e] = *(float4*)(s_stage + p*68 + c4*4);
    }
}

// ---------------- 5) criss-cross attention ----------------
// height==1: CTA = column f; writes g_att channels-last.
// height==0: CTA = row f; reads g_att, fuses full epilogue, writes out (NCHW).
__global__ __launch_bounds__(256, 2)
void k_attn(int height, float* __restrict__ out, const float* __restrict__ gamma) {
    extern __shared__ float sm[];
    float* q_s = sm;            // 256 x 8  (pixel-contiguous)
    float* k_s = sm + 2048;     // 256 x 8
    float* z_s = sm + 4096;     // 256 (invz)
    float* v_s = sm + 4352;     // 256 x 68 (padded)
    int tid = threadIdx.x;
    int b = blockIdx.x >> 8;
    int f = blockIdx.x & 255;

    const float4* gq = (const float4*)(g_q   + (size_t)b*HW*8);
    const float4* gk = (const float4*)(g_k   + (size_t)b*HW*8);
    const float4* gv = (const float4*)(g_val + (size_t)b*HW*64);

    if (height) {
        for (int e = tid; e < 512; e += 256) {
            int j = e >> 1, c4 = e & 1;
            size_t g = ((size_t)j*W + f)*2 + c4;
            ((float4*)q_s)[e] = gq[g];
            ((float4*)k_s)[e] = gk[g];
        }
        for (int e = tid; e < 4096; e += 256) {
            int j = e >> 4, c4 = e & 15;
            *(float4*)(v_s + j*68 + c4*4) = gv[((size_t)j*W + f)*16 + c4];
        }
    } else {
        size_t p0 = (size_t)f * W;
        for (int e = tid; e < 512; e += 256) {
            ((float4*)q_s)[e] = gq[p0*2 + e];
            ((float4*)k_s)[e] = gk[p0*2 + e];
        }
        for (int e = tid; e < 4096; e += 256) {
            int j = e >> 4, c4 = e & 15;
            *(float4*)(v_s + j*68 + c4*4) = gv[p0*16 + e];
        }
    }
    __syncthreads();

    // own q (for pass1) and own k (for pass2), packed
    u64 qr[4], kr[4];
    {
        const ulonglong2* qp = (const ulonglong2*)(q_s + tid*8);
        const ulonglong2* kp = (const ulonglong2*)(k_s + tid*8);
        ulonglong2 t;
        t = qp[0]; qr[0] = t.x; qr[1] = t.y;
        t = qp[1]; qr[2] = t.x; qr[3] = t.y;
        t = kp[0]; kr[0] = t.x; kr[1] = t.y;
        t = kp[1]; kr[2] = t.x; kr[3] = t.y;
    }
    const u64 zero2 = pk2(0.f, 0.f);

    // ---- pass 1 (thread = j): Z_j = sum_i exp(q_j . k_i)  (|s| is tiny; no max shift) ----
    float z = 0.f;
    for (int i = 0; i < 256; i++) {
        const ulonglong2* kp = (const ulonglong2*)(k_s + i*8);   // broadcast
        ulonglong2 k01 = kp[0], k23 = kp[1];
        u64 a0 = fma2(qr[1], k01.y, fma2(qr[0], k01.x, zero2));
        u64 a1 = fma2(qr[3], k23.y, fma2(qr[2], k23.x, zero2));
        float sx, sy; upk2(add2(a0, a1), sx, sy);
        z += __expf(sx + sy);
    }
    z_s[tid] = 1.0f / z;
    __syncthreads();

    // ---- pass 2 (thread = i): out[c,i] = sum_j v[c,j] * exp(q_j . k_i) / Z_j ----
    u64 acc[32];
    #pragma unroll
    for (int u = 0; u < 32; u++) acc[u] = zero2;
    for (int j = 0; j < 256; j++) {
        const ulonglong2* qp = (const ulonglong2*)(q_s + j*8);   // broadcast
        ulonglong2 q01 = qp[0], q23 = qp[1];
        u64 a0 = fma2(kr[1], q01.y, fma2(kr[0], q01.x, zero2));
        u64 a1 = fma2(kr[3], q23.y, fma2(kr[2], q23.x, zero2));
        float sx, sy; upk2(add2(a0, a1), sx, sy);
        float e = __expf(sx + sy) * z_s[j];
        u64 e2 = pk2(e, e);
        const ulonglong2* vr = (const ulonglong2*)(v_s + j*68);  // broadcast
        #pragma unroll
        for (int u = 0; u < 16; u++) {
            ulonglong2 vv = vr[u];
            acc[2*u]   = fma2(e2, vv.x, acc[2*u]);
            acc[2*u+1] = fma2(e2, vv.y, acc[2*u+1]);
        }
    }

    if (height) {
        // stage acc rows -> cooperative channels-last store to g_att
        __syncthreads();
        #pragma unroll
        for (int u = 0; u < 32; u++) {
            float a, bb; upk2(acc[u], a, bb);
            v_s[tid*68 + 2*u]     = a;
            v_s[tid*68 + 2*u + 1] = bb;
        }
        __syncthreads();
        float4* ga = (float4*)(g_att + (size_t)b*HW*64);
        for (int e = tid; e < 4096; e += 256) {
            int j = e >> 4, c4 = e & 15;
            ga[((size_t)j*W + f)*16 + c4] = *(float4*)(v_s + j*68 + c4*4);
        }
    } else {
        // width pass: fuse epilogue. Load h_out row into v_s; al/be pairs into q_s.
        __syncthreads();
        u64* s_al2 = (u64*)q_s;           // 32 pairs
        u64* s_be2 = ((u64*)q_s) + 32;
        if (tid < 32) {
            s_al2[tid] = pk2(g_alpha[b*C + 2*tid], g_alpha[b*C + 2*tid + 1]);
            s_be2[tid] = pk2(g_beta [b*C + 2*tid], g_beta [b*C + 2*tid + 1]);
        }
        const float4* ga = (const float4*)(g_att + ((size_t)b*HW + (size_t)f*W) * 64);
        for (int e = tid; e < 4096; e += 256) {
            int p = e >> 4, c4 = e & 15;
            *(float4*)(v_s + p*68 + c4*4) = ga[e];
        }
        __syncthreads();
        float gm = gamma[0];
        u64 gm2 = pk2(gm, gm);
        size_t obase = (size_t)b*CHW + (size_t)f*W + tid;
        const u64* ar = (const u64*)(v_s + tid*68);
        #pragma unroll
        for (int u = 0; u < 32; u++) {
            u64 hv = add2(ar[u], acc[u]);                       // h_out + v_out
            float y0a = g_y0[obase + (size_t)(2*u)  *HW];
            float y0b = g_y0[obase + (size_t)(2*u+1)*HW];
            u64 y2 = pk2(y0a, y0b);
            u64 r = fma2(gm2, hv, fma2(s_al2[u], y2, s_be2[u]));
            float ra, rb; upk2(r, ra, rb);
            out[obase + (size_t)(2*u)  *HW] = ra;
            out[obase + (size_t)(2*u+1)*HW] = rb;
        }
    }
}

// ---------------- 6) 2x2 maxpool ----------------
__global__ __launch_bounds__(256)
void k_pool(const float* __restrict__ out, float* __restrict__ down) {
    int idx = blockIdx.x * 256 + threadIdx.x;     // [b][c][h2][w2]
    int w2 = idx & 127;
    int r  = idx >> 7;
    int h2 = r & 127;
    int bc = r >> 7;
    size_t p = (size_t)bc*HW + (size_t)(2*h2)*W + 2*w2;
    float2 a = *(const float2*)(out + p);
    float2 bq = *(const float2*)(out + p + W);
    down[idx] = fmaxf(fmaxf(a.x, a.y), fmaxf(bq.x, bq.y));
}

// ---------------- launch ----------------
extern "C" void kernel_launch(void* const* d_in, const int* in_sizes, int n_in,
                              void* d_out, int out_size) {
    const float* x       = (const float*)d_in[0];
    const float* hconv_w = (const float*)d_in[1];
    const float* hconv_b = (const float*)d_in[2];
    const float* vconv_w = (const float*)d_in[3];
    const float* vconv_b = (const float*)d_in[4];
    const float* pw_w    = (const float*)d_in[5];
    const float* pw_b    = (const float*)d_in[6];
    const float* bn_w    = (const float*)d_in[7];
    const float* bn_b    = (const float*)d_in[8];
    const float* q_w     = (const float*)d_in[9];
    const float* q_b     = (const float*)d_in[10];
    const float* k_w     = (const float*)d_in[11];
    const float* k_b     = (const float*)d_in[12];
    const float* v_w     = (const float*)d_in[13];
    const float* v_b     = (const float*)d_in[14];
    const float* gamma   = (const float*)d_in[15];
    float* out = (float*)d_out;

    const int ATTN_SMEM = (4352 + 256*68) * 4;           // 87040 B
    const int QKV_SMEM  = (C*80 + 256*68) * 4;           // 90112 B
    static bool attr_done = false;
    if (!attr_done) {
        cudaFuncSetAttribute(k_attn, cudaFuncAttributeMaxDynamicSharedMemorySize, ATTN_SMEM);
        cudaFuncSetAttribute(k_qkv,  cudaFuncAttributeMaxDynamicSharedMemorySize, QKV_SMEM);
        attr_done = true;
    }

    k_conv_pw<<<BB*H, 256>>>(x, hconv_w, hconv_b, vconv_w, vconv_b, pw_w, pw_b);
    k_istats<<<BB*C, 256>>>();
    k_alphabeta<<<1, 64>>>(bn_w, bn_b);
    k_qkv<<<BB*H, 256, QKV_SMEM>>>(q_w, q_b, k_w, k_b, v_w, v_b);
    k_attn<<<BB*256, 256, ATTN_SMEM>>>(1, nullptr, gamma);   // height pass
    k_attn<<<BB*256, 256, ATTN_SMEM>>>(0, out, gamma);       // width pass + epilogue
    k_pool<<<(TOT/4)/256, 256>>>(out, out + TOT);
}

// round 10
// speedup vs baseline: 2.0752x; 1.0494x over previous
#include <cuda_runtime.h>
#include <math.h>

#define BB 4
#define C 64
#define CQn 8
#define H 256
#define W 256
#define HW 65536
#define CHW (C*HW)          // 4194304
#define TOT (BB*CHW)        // 16777216

typedef unsigned long long u64;

// ---- packed f32x2 helpers ----
__device__ __forceinline__ u64 pk2(float a, float b) {
    u64 r;
    asm("mov.b64 %0, {%1, %2};" : "=l"(r) : "r"(__float_as_uint(a)), "r"(__float_as_uint(b)));
    return r;
}
__device__ __forceinline__ void upk2(u64 v, float& a, float& b) {
    unsigned lo, hi;
    asm("mov.b64 {%0, %1}, %2;" : "=r"(lo), "=r"(hi) : "l"(v));
    a = __uint_as_float(lo); b = __uint_as_float(hi);
}
__device__ __forceinline__ u64 fma2(u64 a, u64 b, u64 c) {
    u64 d;
    asm("fma.rn.f32x2 %0, %1, %2, %3;" : "=l"(d) : "l"(a), "l"(b), "l"(c));
    return d;
}
__device__ __forceinline__ u64 add2(u64 a, u64 b) {
    u64 d;
    asm("add.rn.f32x2 %0, %1, %2;" : "=l"(d) : "l"(a), "l"(b));
    return d;
}

// ---------------- scratch ----------------
__device__ float g_y0[TOT];                 // pre-norm pointwise output (NCHW)
__device__ float g_val[TOT];                // v projection (channels-last [b][h][w][c])
__device__ float g_att[TOT];                // h_out (channels-last [b][i][w][c])
__device__ float g_q[BB*HW*CQn];            // channels-last [b][h][w][8]
__device__ float g_k[BB*HW*CQn];
__device__ float g_isum[BB*C], g_isq[BB*C];
__device__ float g_alpha[BB*C], g_beta[BB*C];

// ---------------- 0) zero the stat accumulators ----------------
__global__ void k_zero() {
    int t = threadIdx.x;
    if (t < BB*C) { g_isum[t] = 0.f; g_isq[t] = 0.f; }
}

// ---------------- 1) axial conv + relu + pointwise + fused instance stats ----------------
__global__ __launch_bounds__(256, 2)
void k_conv_pw(const float* __restrict__ x,
               const float* __restrict__ hw_, const float* __restrict__ hb,
               const float* __restrict__ vw_, const float* __restrict__ vb,
               const float* __restrict__ pww, const float* __restrict__ pwb) {
    extern __shared__ float s_stage[];      // 256 x 68
    __shared__ float s_hw[C*5], s_vw[C*5], s_hb[C], s_vb[C];
    __shared__ float s_pwT[C*C];            // [c][o] transposed
    __shared__ u64   s_pwb2[C/2];
    int tid = threadIdx.x;
    for (int i = tid; i < C*5; i += 256) { s_hw[i] = hw_[i]; s_vw[i] = vw_[i]; }
    for (int i = tid; i < C;   i += 256) { s_hb[i] = hb[i]; s_vb[i] = vb[i]; }
    for (int i = tid; i < C*C; i += 256) { int o = i >> 6, c = i & 63; s_pwT[c*C + o] = pww[i]; }
    if (tid < C/2) s_pwb2[tid] = pk2(pwb[2*tid], pwb[2*tid+1]);
    __syncthreads();

    int row = blockIdx.x;
    int b = row >> 8, h = row & 255;
    int w = tid;
    const float* xb = x + (size_t)b * CHW;

    u64 acc[C/2];
    #pragma unroll
    for (int o = 0; o < C/2; o++) acc[o] = s_pwb2[o];

    for (int c = 0; c < C; c++) {
        const float* xc = xb + c * HW + h * W;
        float center = xc[w];
        float hs = s_hb[c], vs = s_vb[c];
        #pragma unroll
        for (int t = 0; t < 5; t++) {
            int ww = w + t - 2;
            float xv = (ww >= 0 && ww < W) ? xc[ww] : 0.f;
            hs = fmaf(s_hw[c*5 + t], xv, hs);
            int hh = h + t - 2;
            float xv2 = (hh >= 0 && hh < H) ? xb[c*HW + hh*W + w] : 0.f;
            vs = fmaf(s_vw[c*5 + t], xv2, vs);
        }
        float a = hs + vs + center;
        a = a > 0.f ? a : 0.f;
        u64 a2 = pk2(a, a);
        const ulonglong2* wr = (const ulonglong2*)(s_pwT + c*C);
        #pragma unroll
        for (int o = 0; o < C/4; o++) {
            ulonglong2 ww = wr[o];
            acc[2*o]   = fma2(a2, ww.x, acc[2*o]);
            acc[2*o+1] = fma2(a2, ww.y, acc[2*o+1]);
        }
    }
    size_t base = (size_t)b * CHW + h * W + w;
    #pragma unroll
    for (int o = 0; o < C/2; o++) {
        float a, bb; upk2(acc[o], a, bb);
        g_y0[base + (size_t)(2*o)   * HW] = a;
        g_y0[base + (size_t)(2*o+1) * HW] = bb;
        s_stage[tid*68 + 2*o]     = a;
        s_stage[tid*68 + 2*o + 1] = bb;
    }
    __syncthreads();
    // fused per-(b,c) partial stats: thread t sums channel (t&63) over 64 pixels
    {
        int ch = tid & 63, pb = tid >> 6;
        float s = 0.f, qq = 0.f;
        #pragma unroll 8
        for (int p = pb*64; p < pb*64 + 64; p++) {
            float v = s_stage[p*68 + ch];
            s += v; qq = fmaf(v, v, qq);
        }
        atomicAdd(&g_isum[b*C + ch], s);
        atomicAdd(&g_isq [b*C + ch], qq);
    }
}

// ---------------- 3) hybrid-norm -> per-(b,c) affine alpha,beta ----------------
__global__ void k_alphabeta(const float* __restrict__ bn_w, const float* __restrict__ bn_b) {
    int c = threadIdx.x;
    if (c >= C) return;
    const float EPS = 1e-5f, R = 0.7f, R1 = 0.3f;
    float im[BB], iv[BB];
    float bm = 0.f, ey2 = 0.f;
    for (int b = 0; b < BB; b++) {
        float s  = g_isum[b*C + c] * (1.0f/HW);
        float sq = g_isq [b*C + c] * (1.0f/HW);
        im[b] = s; iv[b] = sq - s*s;
        bm += s; ey2 += sq;
    }
    bm *= 0.25f; ey2 *= 0.25f;
    float bv = ey2 - bm*bm;
    float rB = rsqrtf(bv + EPS);
    float w = bn_w[c], bb = bn_b[c];
    for (int b = 0; b < BB; b++) {
        float rI = rsqrtf(iv[b] + EPS);
        g_alpha[b*C + c] = R*rI + R1*rB*w;
        g_beta [b*C + c] = -R*im[b]*rI + R1*(bb - bm*rB*w);
    }
}

// ---------------- 4) q/k/v projections (chunked prefetch, f32x2) ----------------
__global__ __launch_bounds__(256, 2)
void k_qkv(const float* __restrict__ qw, const float* __restrict__ qb,
           const float* __restrict__ kw, const float* __restrict__ kb,
           const float* __restrict__ vw, const float* __restrict__ vb) {
    extern __shared__ float sm[];
    float* s_wT    = sm;                    // 64 x 80 : [c][o]  o: 0-7 q, 8-15 k, 16-79 v
    float* s_stage = sm + C*80;             // 256 x 68 (padded)
    __shared__ float s_al[C], s_be[C];
    __shared__ u64   s_b2[40];
    int tid = threadIdx.x;
    int b = blockIdx.x >> 8, h = blockIdx.x & 255;

    for (int i = tid; i < CQn*C; i += 256) {
        int o = i >> 6, c = i & 63;
        s_wT[c*80 + o]     = qw[i];
        s_wT[c*80 + 8 + o] = kw[i];
    }
    for (int i = tid; i < C*C; i += 256) {
        int o = i >> 6, c = i & 63;
        s_wT[c*80 + 16 + o] = vw[i];
    }
    if (tid < 4)                 s_b2[tid] = pk2(qb[2*tid],        qb[2*tid+1]);
    else if (tid < 8)            s_b2[tid] = pk2(kb[2*(tid-4)],    kb[2*(tid-4)+1]);
    else if (tid < 40)           s_b2[tid] = pk2(vb[2*(tid-8)],    vb[2*(tid-8)+1]);
    if (tid < C) { s_al[tid] = g_alpha[b*C + tid]; s_be[tid] = g_beta[b*C + tid]; }
    __syncthreads();

    u64 acc[40];
    #pragma unroll
    for (int o = 0; o < 40; o++) acc[o] = s_b2[o];

    size_t ybase = (size_t)b * CHW + h * W + tid;
    float yv[16];
    for (int cb = 0; cb < C; cb += 16) {
        #pragma unroll
        for (int u = 0; u < 16; u++) yv[u] = g_y0[ybase + (size_t)(cb + u) * HW];
        #pragma unroll
        for (int u = 0; u < 16; u++) {
            int c = cb + u;
            float y = fmaf(s_al[c], yv[u], s_be[c]);
            u64 y2 = pk2(y, y);
            const ulonglong2* wr = (const ulonglong2*)(s_wT + c*80);
            #pragma unroll
            for (int o = 0; o < 20; o++) {
                ulonglong2 ww = wr[o];
                acc[2*o]   = fma2(y2, ww.x, acc[2*o]);
                acc[2*o+1] = fma2(y2, ww.y, acc[2*o+1]);
            }
        }
    }

    // q, k: per-thread float4 writes (channels-last)
    size_t pq = ((size_t)b*HW + h*W + tid) * 8;
    {
        float a0,a1,a2,a3;
        upk2(acc[0], a0, a1); upk2(acc[1], a2, a3);
        *(float4*)(g_q + pq) = make_float4(a0,a1,a2,a3);
        upk2(acc[2], a0, a1); upk2(acc[3], a2, a3);
        *(float4*)(g_q + pq + 4) = make_float4(a0,a1,a2,a3);
        upk2(acc[4], a0, a1); upk2(acc[5], a2, a3);
        *(float4*)(g_k + pq) = make_float4(a0,a1,a2,a3);
        upk2(acc[6], a0, a1); upk2(acc[7], a2, a3);
        *(float4*)(g_k + pq + 4) = make_float4(a0,a1,a2,a3);
    }
    // v: stage to smem (padded), then cooperative coalesced store
    #pragma unroll
    for (int u = 0; u < 32; u++) {
        float a, bb; upk2(acc[8 + u], a, bb);
        s_stage[tid*68 + 2*u]     = a;
        s_stage[tid*68 + 2*u + 1] = bb;
    }
    __syncthreads();
    float4* gv = (float4*)(g_val + ((size_t)b*HW + h*W) * 64);
    for (int e = tid; e < 4096; e += 256) {
        int p = e >> 4, c4 = e & 15;
        gv[e] = *(float4*)(s_stage + p*68 + c4*4);
    }
}

// ---------------- 5) criss-cross attention: 128 threads, 2 pixels/thread ----------------
// height==1: CTA = column f; writes g_att channels-last.
// height==0: CTA = row f; reads g_att, fuses full epilogue, writes out (NCHW).
__global__ __launch_bounds__(128)
void k_attn(int height, float* __restrict__ out, const float* __restrict__ gamma) {
    extern __shared__ float sm[];
    float* q_s = sm;            // 256 x 8  (pixel-contiguous)
    float* k_s = sm + 2048;     // 256 x 8
    float* z_s = sm + 4096;     // 256 (invz)
    float* v_s = sm + 4352;     // 256 x 68 (padded)
    int tid = threadIdx.x;
    int b = blockIdx.x >> 8;
    int f = blockIdx.x & 255;
    int p0 = tid, p1 = tid + 128;

    const float4* gq = (const float4*)(g_q   + (size_t)b*HW*8);
    const float4* gk = (const float4*)(g_k   + (size_t)b*HW*8);
    const float4* gv = (const float4*)(g_val + (size_t)b*HW*64);

    if (height) {
        for (int e = tid; e < 512; e += 128) {
            int j = e >> 1, c4 = e & 1;
            size_t g = ((size_t)j*W + f)*2 + c4;
            ((float4*)q_s)[e] = gq[g];
            ((float4*)k_s)[e] = gk[g];
        }
        for (int e = tid; e < 4096; e += 128) {
            int j = e >> 4, c4 = e & 15;
            *(float4*)(v_s + j*68 + c4*4) = gv[((size_t)j*W + f)*16 + c4];
        }
    } else {
        size_t pb = (size_t)f * W;
        for (int e = tid; e < 512; e += 128) {
            ((float4*)q_s)[e] = gq[pb*2 + e];
            ((float4*)k_s)[e] = gk[pb*2 + e];
        }
        for (int e = tid; e < 4096; e += 128) {
            int j = e >> 4, c4 = e & 15;
            *(float4*)(v_s + j*68 + c4*4) = gv[pb*16 + e];
        }
    }
    __syncthreads();

    const u64 zero2 = pk2(0.f, 0.f);

    // own k vectors for the two output pixels (used in pass 2)
    u64 k0r[4], k1r[4];
    {
        const ulonglong2* kp0 = (const ulonglong2*)(k_s + p0*8);
        const ulonglong2* kp1 = (const ulonglong2*)(k_s + p1*8);
        ulonglong2 t;
        t = kp0[0]; k0r[0] = t.x; k0r[1] = t.y;
        t = kp0[1]; k0r[2] = t.x; k0r[3] = t.y;
        t = kp1[0]; k1r[0] = t.x; k1r[1] = t.y;
        t = kp1[1]; k1r[2] = t.x; k1r[3] = t.y;
    }

    // ---- pass 1 (thread = sources j=p0, j=p1): Z_j = sum_i exp(q_j . k_i) ----
    {
        u64 q0r[4], q1r[4];
        const ulonglong2* qp0 = (const ulonglong2*)(q_s + p0*8);
        const ulonglong2* qp1 = (const ulonglong2*)(q_s + p1*8);
        ulonglong2 t;
        t = qp0[0]; q0r[0] = t.x; q0r[1] = t.y;
        t = qp0[1]; q0r[2] = t.x; q0r[3] = t.y;
        t = qp1[0]; q1r[0] = t.x; q1r[1] = t.y;
        t = qp1[1]; q1r[2] = t.x; q1r[3] = t.y;
        float z0 = 0.f, z1 = 0.f;
        for (int i = 0; i < 256; i++) {
            const ulonglong2* kp = (const ulonglong2*)(k_s + i*8);   // broadcast
            ulonglong2 k01 = kp[0], k23 = kp[1];
            u64 a0 = fma2(q0r[1], k01.y, fma2(q0r[0], k01.x, zero2));
            u64 a1 = fma2(q0r[3], k23.y, fma2(q0r[2], k23.x, zero2));
            float sx, sy; upk2(add2(a0, a1), sx, sy);
            z0 += __expf(sx + sy);
            u64 b0 = fma2(q1r[1], k01.y, fma2(q1r[0], k01.x, zero2));
            u64 b1 = fma2(q1r[3], k23.y, fma2(q1r[2], k23.x, zero2));
            upk2(add2(b0, b1), sx, sy);
            z1 += __expf(sx + sy);
        }
        z_s[p0] = 1.0f / z0;
        z_s[p1] = 1.0f / z1;
    }
    __syncthreads();

    // ---- pass 2 (thread = outputs i=p0, i=p1) ----
    u64 acc0[32], acc1[32];
    #pragma unroll
    for (int u = 0; u < 32; u++) { acc0[u] = zero2; acc1[u] = zero2; }
    for (int j = 0; j < 256; j++) {
        const ulonglong2* qp = (const ulonglong2*)(q_s + j*8);       // broadcast
        ulonglong2 q01 = qp[0], q23 = qp[1];
        u64 a0 = fma2(k0r[1], q01.y, fma2(k0r[0], q01.x, zero2));
        u64 a1 = fma2(k0r[3], q23.y, fma2(k0r[2], q23.x, zero2));
        float sx, sy; upk2(add2(a0, a1), sx, sy);
        float izj = z_s[j];
        float e0 = __expf(sx + sy) * izj;
        u64 b0 = fma2(k1r[1], q01.y, fma2(k1r[0], q01.x, zero2));
        u64 b1 = fma2(k1r[3], q23.y, fma2(k1r[2], q23.x, zero2));
        upk2(add2(b0, b1), sx, sy);
        float e1 = __expf(sx + sy) * izj;
        u64 e02 = pk2(e0, e0), e12 = pk2(e1, e1);
        const ulonglong2* vr = (const ulonglong2*)(v_s + j*68);      // broadcast
        #pragma unroll
        for (int u = 0; u < 16; u++) {
            ulonglong2 vv = vr[u];
            acc0[2*u]   = fma2(e02, vv.x, acc0[2*u]);
            acc0[2*u+1] = fma2(e02, vv.y, acc0[2*u+1]);
            acc1[2*u]   = fma2(e12, vv.x, acc1[2*u]);
            acc1[2*u+1] = fma2(e12, vv.y, acc1[2*u+1]);
        }
    }

    if (height) {
        __syncthreads();
        #pragma unroll
        for (int u = 0; u < 32; u++) {
            float a, bb;
            upk2(acc0[u], a, bb);
            v_s[p0*68 + 2*u] = a; v_s[p0*68 + 2*u + 1] = bb;
            upk2(acc1[u], a, bb);
            v_s[p1*68 + 2*u] = a; v_s[p1*68 + 2*u + 1] = bb;
        }
        __syncthreads();
        float4* ga = (float4*)(g_att + (size_t)b*HW*64);
        for (int e = tid; e < 4096; e += 128) {
            int j = e >> 4, c4 = e & 15;
            ga[((size_t)j*W + f)*16 + c4] = *(float4*)(v_s + j*68 + c4*4);
        }
    } else {
        // width pass: fuse epilogue. Stage h_out row; al/be pairs into q_s.
        __syncthreads();
        u64* s_al2 = (u64*)q_s;           // 32 pairs
        u64* s_be2 = ((u64*)q_s) + 32;
        if (tid < 32) {
            s_al2[tid] = pk2(g_alpha[b*C + 2*tid], g_alpha[b*C + 2*tid + 1]);
            s_be2[tid] = pk2(g_beta [b*C + 2*tid], g_beta [b*C + 2*tid + 1]);
        }
        const float4* ga = (const float4*)(g_att + ((size_t)b*HW + (size_t)f*W) * 64);
        for (int e = tid; e < 4096; e += 128) {
            int p = e >> 4, c4 = e & 15;
            *(float4*)(v_s + p*68 + c4*4) = ga[e];
        }
        __syncthreads();
        float gm = gamma[0];
        u64 gm2 = pk2(gm, gm);
        size_t obase = (size_t)b*CHW + (size_t)f*W;
        const u64* ar0 = (const u64*)(v_s + p0*68);
        const u64* ar1 = (const u64*)(v_s + p1*68);
        #pragma unroll
        for (int u = 0; u < 32; u++) {
            u64 hv0 = add2(ar0[u], acc0[u]);
            u64 y20 = pk2(g_y0[obase + (size_t)(2*u)*HW + p0], g_y0[obase + (size_t)(2*u+1)*HW + p0]);
            u64 r0 = fma2(gm2, hv0, fma2(s_al2[u], y20, s_be2[u]));
            float ra, rb; upk2(r0, ra, rb);
            out[obase + (size_t)(2*u)  *HW + p0] = ra;
            out[obase + (size_t)(2*u+1)*HW + p0] = rb;
            u64 hv1 = add2(ar1[u], acc1[u]);
            u64 y21 = pk2(g_y0[obase + (size_t)(2*u)*HW + p1], g_y0[obase + (size_t)(2*u+1)*HW + p1]);
            u64 r1 = fma2(gm2, hv1, fma2(s_al2[u], y21, s_be2[u]));
            upk2(r1, ra, rb);
            out[obase + (size_t)(2*u)  *HW + p1] = ra;
            out[obase + (size_t)(2*u+1)*HW + p1] = rb;
        }
    }
}

// ---------------- 6) 2x2 maxpool ----------------
__global__ __launch_bounds__(256)
void k_pool(const float* __restrict__ out, float* __restrict__ down) {
    int idx = blockIdx.x * 256 + threadIdx.x;     // [b][c][h2][w2]
    int w2 = idx & 127;
    int r  = idx >> 7;
    int h2 = r & 127;
    int bc = r >> 7;
    size_t p = (size_t)bc*HW + (size_t)(2*h2)*W + 2*w2;
    float2 a = *(const float2*)(out + p);
    float2 bq = *(const float2*)(out + p + W);
    down[idx] = fmaxf(fmaxf(a.x, a.y), fmaxf(bq.x, bq.y));
}

// ---------------- launch ----------------
extern "C" void kernel_launch(void* const* d_in, const int* in_sizes, int n_in,
                              void* d_out, int out_size) {
    const float* x       = (const float*)d_in[0];
    const float* hconv_w = (const float*)d_in[1];
    const float* hconv_b = (const float*)d_in[2];
    const float* vconv_w = (const float*)d_in[3];
    const float* vconv_b = (const float*)d_in[4];
    const float* pw_w    = (const float*)d_in[5];
    const float* pw_b    = (const float*)d_in[6];
    const float* bn_w    = (const float*)d_in[7];
    const float* bn_b    = (const float*)d_in[8];
    const float* q_w     = (const float*)d_in[9];
    const float* q_b     = (const float*)d_in[10];
    const float* k_w     = (const float*)d_in[11];
    const float* k_b     = (const float*)d_in[12];
    const float* v_w     = (const float*)d_in[13];
    const float* v_b     = (const float*)d_in[14];
    const float* gamma   = (const float*)d_in[15];
    float* out = (float*)d_out;

    const int ATTN_SMEM = (4352 + 256*68) * 4;           // 87040 B
    const int QKV_SMEM  = (C*80 + 256*68) * 4;           // 90112 B
    const int CONV_SMEM = (256*68) * 4;                  // 69632 B
    static bool attr_done = false;
    if (!attr_done) {
        cudaFuncSetAttribute(k_attn,    cudaFuncAttributeMaxDynamicSharedMemorySize, ATTN_SMEM);
        cudaFuncSetAttribute(k_qkv,     cudaFuncAttributeMaxDynamicSharedMemorySize, QKV_SMEM);
        cudaFuncSetAttribute(k_conv_pw, cudaFuncAttributeMaxDynamicSharedMemorySize, CONV_SMEM);
        attr_done = true;
    }

    k_zero<<<1, 256>>>();
    k_conv_pw<<<BB*H, 256, CONV_SMEM>>>(x, hconv_w, hconv_b, vconv_w, vconv_b, pw_w, pw_b);
    k_alphabeta<<<1, 64>>>(bn_w, bn_b);
    k_qkv<<<BB*H, 256, QKV_SMEM>>>(q_w, q_b, k_w, k_b, v_w, v_b);
    k_attn<<<BB*256, 128, ATTN_SMEM>>>(1, nullptr, gamma);   // height pass
    k_attn<<<BB*256, 128, ATTN_SMEM>>>(0, out, gamma);       // width pass + epilogue
    k_pool<<<(TOT/4)/256, 256>>>(out, out + TOT);
}